// round 1
// baseline (speedup 1.0000x reference)
#include <cuda_runtime.h>
#include <cuda_pipeline.h>
#include <mma.h>
#include <math.h>

using namespace nvcuda;

#define B_   16384
#define S_   6
#define D_   991
#define KD   992          // padded K (D + 1)
#define G3   2973         // 3*D
#define NP   3072         // padded N for GEMM tiles
#define NT_  (NP / 128)   // 24 N-tiles

// ------------------- scratch (device globals; no allocation allowed) ------
__device__ float g_x  [(size_t)B_ * S_ * KD];   // LN'd embeddings, [s*B+b][KD]
__device__ float g_xg [(size_t)S_ * B_ * NP];   // input gates, [s][b][NP]
__device__ float g_gh [(size_t)B_ * NP];        // recurrent gates per step
__device__ float g_h  [(size_t)B_ * KD];        // hidden state
__device__ float g_out[(size_t)B_ * KD];        // gathered last-step hidden
__device__ float g_Wih[(size_t)NP * KD];        // padded W_ih
__device__ float g_Whh[(size_t)NP * KD];        // padded W_hh
__device__ float g_bih[NP];
__device__ float g_bhh[NP];
__device__ float g_psum[32 * KD];
__device__ float g_psq [32 * KD];
__device__ float g_weff[2 * D_];                // W2 @ W1
__device__ float g_wbn [2 * KD];                // weff * bn scale
__device__ float g_shift[KD];
__device__ float g_bbn [2];

// --------------------------- small helpers --------------------------------
__device__ __forceinline__ float2 block_reduce2(float a, float b) {
    __shared__ float wa[8], wb[8];
    __shared__ float ra, rb;
    int lane = threadIdx.x & 31, w = threadIdx.x >> 5;
#pragma unroll
    for (int o = 16; o; o >>= 1) {
        a += __shfl_down_sync(0xffffffffu, a, o);
        b += __shfl_down_sync(0xffffffffu, b, o);
    }
    if (!lane) { wa[w] = a; wb[w] = b; }
    __syncthreads();
    if (threadIdx.x < 8) { a = wa[threadIdx.x]; b = wb[threadIdx.x]; }
    else { a = 0.f; b = 0.f; }
    if (w == 0) {
#pragma unroll
        for (int o = 4; o; o >>= 1) {
            a += __shfl_down_sync(0xffffffffu, a, o);
            b += __shfl_down_sync(0xffffffffu, b, o);
        }
    }
    if (threadIdx.x == 0) { ra = a; rb = b; }
    __syncthreads();
    return make_float2(ra, rb);
}

// --------------------------- init / pack ----------------------------------
__global__ void zero_h_kernel() {
    size_t i = (size_t)blockIdx.x * 256 + threadIdx.x;
    if (i < (size_t)B_ * KD) g_h[i] = 0.f;
}

__global__ void pad_weights(const float* __restrict__ Wih, const float* __restrict__ Whh,
                            const float* __restrict__ bih, const float* __restrict__ bhh) {
    int i = blockIdx.x * 256 + threadIdx.x;
    if (i >= NP * KD) return;
    int r = i / KD, c = i - r * KD;
    float vi = 0.f, vh = 0.f;
    if (r < G3 && c < D_) {
        vi = Wih[(size_t)r * D_ + c];
        vh = Whh[(size_t)r * D_ + c];
    }
    g_Wih[i] = vi;
    g_Whh[i] = vh;
    if (c == 0) {
        g_bih[r] = (r < G3) ? bih[r] : 0.f;
        g_bhh[r] = (r < G3) ? bhh[r] : 0.f;
    }
}

// --------------------------- embed + layernorm ----------------------------
__global__ void embed_ln(const int* __restrict__ ns, const int* __restrict__ fs,
                         const int* __restrict__ nfs, const int* __restrict__ ms,
                         const float* __restrict__ ntab, const float* __restrict__ ftab,
                         const float* __restrict__ nftab, const float* __restrict__ btab,
                         const float* __restrict__ lng, const float* __restrict__ lnb) {
    const int bid = blockIdx.x;          // row = s*B + b
    const int s = bid >> 14;             // B_ = 2^14
    const int b = bid & (B_ - 1);
    __shared__ float srow[D_];
    const int q = b * S_ + s;
    const int ni = ns[q], fi = fs[q], nfi = nfs[q], mi = ms[q];
    float s1 = 0.f, s2 = 0.f;
    for (int d = threadIdx.x; d < D_; d += 256) {
        float v;
        if (d < 128)      v = ntab[(size_t)ni * 128 + d];
        else if (d < 212) v = ftab[(size_t)fi * 84 + (d - 128)];
        else if (d < 223) v = nftab[(size_t)nfi * 11 + (d - 212)];
        else              v = btab[(size_t)mi * 768 + (d - 223)];
        srow[d] = v;
        s1 += v; s2 += v * v;
    }
    float2 t = block_reduce2(s1, s2);
    const float mu  = t.x * (1.f / 991.f);
    const float var = fmaxf(t.y * (1.f / 991.f) - mu * mu, 0.f);
    const float rs  = rsqrtf(var + 1e-5f);
    float* xr = g_x + (size_t)bid * KD;
    for (int d = threadIdx.x; d < D_; d += 256)
        xr[d] = (srow[d] - mu) * rs * lng[d] + lnb[d];
    if (threadIdx.x == 0) xr[D_] = 0.f;   // K padding column
}

// --------------------------- TF32 GEMM: C = A * B^T + bias ----------------
// A: [M, K] lda;  B: [Npad, K] ldb (row-major, K-major);  C: [M, Npad] ldc
// 128x128x16 block tile, 8 warps of 32x64, wmma m16n16k8 tf32, cp.async DB.
__device__ __forceinline__ void ld_tile(const float* __restrict__ G, int ld,
                                        int r0, int k0, float (*s)[20], int tid) {
#pragma unroll
    for (int i = 0; i < 2; ++i) {
        int id  = tid + i * 256;
        int row = id >> 2;
        int col = (id & 3) << 2;
        __pipeline_memcpy_async(&s[row][col], G + (size_t)(r0 + row) * ld + k0 + col, 16);
    }
}

__global__ void __launch_bounds__(256, 2)
gemm_tf32(const float* __restrict__ A, const float* __restrict__ Bm,
          float* __restrict__ C, const float* __restrict__ bias,
          int lda, int ldb, int ldc, int nTiles, int K) {
    __shared__ alignas(128) float sA[2][128][20];
    __shared__ alignas(128) float sB[2][128][20];
    const int tid = threadIdx.x;
    const int mt = blockIdx.x / nTiles, nt = blockIdx.x % nTiles;
    const int m0 = mt * 128, n0 = nt * 128;
    const int warp = tid >> 5;
    const int mb = (warp >> 1) * 32, nb = (warp & 1) * 64;

    wmma::fragment<wmma::accumulator, 16, 16, 8, float> acc[2][4];
#pragma unroll
    for (int i = 0; i < 2; i++)
#pragma unroll
        for (int j = 0; j < 4; j++) wmma::fill_fragment(acc[i][j], 0.f);

    const int KT = K >> 4;
    ld_tile(A,  lda, m0, 0, sA[0], tid);
    ld_tile(Bm, ldb, n0, 0, sB[0], tid);
    __pipeline_commit();

    for (int kt = 0; kt < KT; ++kt) {
        const int cur = kt & 1;
        if (kt + 1 < KT) {
            ld_tile(A,  lda, m0, (kt + 1) << 4, sA[cur ^ 1], tid);
            ld_tile(Bm, ldb, n0, (kt + 1) << 4, sB[cur ^ 1], tid);
            __pipeline_commit();
            __pipeline_wait_prior(1);
        } else {
            __pipeline_wait_prior(0);
        }
        __syncthreads();
#pragma unroll
        for (int ki = 0; ki < 16; ki += 8) {
            wmma::fragment<wmma::matrix_a, 16, 16, 8, wmma::precision::tf32, wmma::row_major> af[2];
            wmma::fragment<wmma::matrix_b, 16, 16, 8, wmma::precision::tf32, wmma::col_major> bf[4];
#pragma unroll
            for (int i = 0; i < 2; i++) {
                wmma::load_matrix_sync(af[i], &sA[cur][mb + i * 16][ki], 20);
#pragma unroll
                for (int t = 0; t < af[i].num_elements; t++)
                    af[i].x[t] = wmma::__float_to_tf32(af[i].x[t]);
            }
#pragma unroll
            for (int j = 0; j < 4; j++) {
                wmma::load_matrix_sync(bf[j], &sB[cur][nb + j * 16][ki], 20);
#pragma unroll
                for (int t = 0; t < bf[j].num_elements; t++)
                    bf[j].x[t] = wmma::__float_to_tf32(bf[j].x[t]);
            }
#pragma unroll
            for (int i = 0; i < 2; i++)
#pragma unroll
                for (int j = 0; j < 4; j++)
                    wmma::mma_sync(acc[i][j], af[i], bf[j], acc[i][j]);
        }
        __syncthreads();   // also guards smem reuse by the epilogue stage
    }

    // epilogue: stage 16x16 frags in smem, add bias, vectorized store
    float* stage = &sA[0][0][0] + warp * 256;
    const int lane = tid & 31;
    const int r  = lane >> 1;
    const int c0 = (lane & 1) * 8;
#pragma unroll
    for (int i = 0; i < 2; i++)
#pragma unroll
        for (int j = 0; j < 4; j++) {
            wmma::store_matrix_sync(stage, acc[i][j], 16, wmma::mem_row_major);
            __syncwarp();
            const int gr = m0 + mb + i * 16 + r;
            const int gc = n0 + nb + j * 16 + c0;
            float4 v0 = *(const float4*)(stage + r * 16 + c0);
            float4 v1 = *(const float4*)(stage + r * 16 + c0 + 4);
            const float4 b0 = *(const float4*)(bias + gc);
            const float4 b1 = *(const float4*)(bias + gc + 4);
            v0.x += b0.x; v0.y += b0.y; v0.z += b0.z; v0.w += b0.w;
            v1.x += b1.x; v1.y += b1.y; v1.z += b1.z; v1.w += b1.w;
            *(float4*)(C + (size_t)gr * ldc + gc)     = v0;
            *(float4*)(C + (size_t)gr * ldc + gc + 4) = v1;
            __syncwarp();
        }
}

// --------------------------- GRU cell (elementwise) -----------------------
__global__ void gru_cell(const int* __restrict__ seq_len, int t) {
    unsigned i = blockIdx.x * 256u + threadIdx.x;
    if (i >= (unsigned)B_ * D_) return;
    int b = i / D_;
    int d = i - b * D_;
    const float* xg = g_xg + (size_t)t * B_ * NP + (size_t)b * NP;
    const float* gh = g_gh + (size_t)b * NP;
    float r = 1.f / (1.f + expf(-(xg[d]        + gh[d])));
    float z = 1.f / (1.f + expf(-(xg[D_ + d]   + gh[D_ + d])));
    float n = tanhf(xg[2 * D_ + d] + r * gh[2 * D_ + d]);
    float hp = g_h[(size_t)b * KD + d];
    float hv = (1.f - z) * n + z * hp;
    g_h[(size_t)b * KD + d] = hv;
    if (seq_len[b] - 1 == t) g_out[(size_t)b * KD + d] = hv;
}

// --------------------------- batchnorm stats (deterministic 2-stage) ------
__global__ void bn_partial() {
    __shared__ float ss[8][33], sq[8][33];
    int col = blockIdx.x * 32 + threadIdx.x;     // 0..991
    int ty = threadIdx.y;
    float s = 0.f, q = 0.f;
    for (int r = blockIdx.y * 8 + ty; r < B_; r += 256) {
        float v = g_out[(size_t)r * KD + col];
        s += v; q += v * v;
    }
    ss[ty][threadIdx.x] = s; sq[ty][threadIdx.x] = q;
    __syncthreads();
    if (ty == 0) {
        float S = 0.f, Q = 0.f;
#pragma unroll
        for (int k = 0; k < 8; k++) { S += ss[k][threadIdx.x]; Q += sq[k][threadIdx.x]; }
        g_psum[blockIdx.y * KD + col] = S;
        g_psq [blockIdx.y * KD + col] = Q;
    }
}

// weff = W2 @ W1  (head collapse, 2 x 991)
__global__ void weff_kernel(const float* __restrict__ W2, const float* __restrict__ W1) {
    int i = blockIdx.x * 256 + threadIdx.x;
    if (i >= 2 * D_) return;
    int o = i / D_, d = i - o * D_;
    float acc = 0.f;
    for (int j = 0; j < 2 * D_; j++)
        acc += W2[o * (2 * D_) + j] * W1[(size_t)j * D_ + d];
    g_weff[i] = acc;
}

__global__ void bn_finalize(const float* __restrict__ bn_g, const float* __restrict__ bn_b) {
    int d = blockIdx.x * 256 + threadIdx.x;
    if (d >= D_) return;
    float s = 0.f, q = 0.f;
#pragma unroll
    for (int p = 0; p < 32; p++) { s += g_psum[p * KD + d]; q += g_psq[p * KD + d]; }
    float mu  = s * (1.f / 16384.f);
    float var = fmaxf(q * (1.f / 16384.f) - mu * mu, 0.f);
    float sc  = bn_g[d] * rsqrtf(var + 1e-4f);
    g_shift[d]    = bn_b[d] - mu * sc;
    g_wbn[d]      = g_weff[d]       * sc;
    g_wbn[KD + d] = g_weff[D_ + d]  * sc;
}

__global__ void bbn_kernel(const float* __restrict__ W2, const float* __restrict__ b1,
                           const float* __restrict__ b2) {
    int o = blockIdx.x;
    float acc = 0.f;
    for (int j = threadIdx.x; j < 2 * D_; j += 256) acc += W2[o * (2 * D_) + j] * b1[j];
    for (int d = threadIdx.x; d < D_; d += 256)     acc += g_weff[o * D_ + d] * g_shift[d];
    float2 t = block_reduce2(acc, 0.f);
    if (threadIdx.x == 0) g_bbn[o] = t.x + b2[o];
}

__global__ void logits_kernel(float* __restrict__ out) {
    int gw   = (blockIdx.x * 256 + threadIdx.x) >> 5;
    int lane = threadIdx.x & 31;
    if (gw >= B_) return;
    const float* row = g_out + (size_t)gw * KD;
    float a0 = 0.f, a1 = 0.f;
    for (int d = lane; d < D_; d += 32) {
        float v = row[d];
        a0 += v * g_wbn[d];
        a1 += v * g_wbn[KD + d];
    }
#pragma unroll
    for (int o = 16; o; o >>= 1) {
        a0 += __shfl_down_sync(0xffffffffu, a0, o);
        a1 += __shfl_down_sync(0xffffffffu, a1, o);
    }
    if (lane == 0) {
        out[2 * gw]     = a0 + g_bbn[0];
        out[2 * gw + 1] = a1 + g_bbn[1];
    }
}

// --------------------------- launch ---------------------------------------
extern "C" void kernel_launch(void* const* d_in, const int* in_sizes, int n_in,
                              void* d_out, int out_size) {
    const int*   node_seq   = (const int*)d_in[0];
    const int*   fin_seq    = (const int*)d_in[1];
    const int*   nfin_seq   = (const int*)d_in[2];
    const int*   mda_seq    = (const int*)d_in[3];
    const int*   seq_len    = (const int*)d_in[4];
    const float* node_table = (const float*)d_in[5];
    const float* fin_table  = (const float*)d_in[6];
    const float* nfin_table = (const float*)d_in[7];
    const float* bert_table = (const float*)d_in[8];
    const float* ln_g = (const float*)d_in[9];
    const float* ln_b = (const float*)d_in[10];
    const float* W_ih = (const float*)d_in[11];
    const float* W_hh = (const float*)d_in[12];
    const float* b_ih = (const float*)d_in[13];
    const float* b_hh = (const float*)d_in[14];
    const float* bn_g = (const float*)d_in[15];
    const float* bn_b = (const float*)d_in[16];
    const float* W1   = (const float*)d_in[17];
    const float* b1   = (const float*)d_in[18];
    const float* W2   = (const float*)d_in[19];
    const float* b2   = (const float*)d_in[20];

    float *px, *pxg, *pgh, *ph, *pWih, *pWhh, *pbih, *pbhh;
    cudaGetSymbolAddress((void**)&px,   g_x);
    cudaGetSymbolAddress((void**)&pxg,  g_xg);
    cudaGetSymbolAddress((void**)&pgh,  g_gh);
    cudaGetSymbolAddress((void**)&ph,   g_h);
    cudaGetSymbolAddress((void**)&pWih, g_Wih);
    cudaGetSymbolAddress((void**)&pWhh, g_Whh);
    cudaGetSymbolAddress((void**)&pbih, g_bih);
    cudaGetSymbolAddress((void**)&pbhh, g_bhh);

    zero_h_kernel<<<(B_ * KD + 255) / 256, 256>>>();
    pad_weights<<<(NP * KD + 255) / 256, 256>>>(W_ih, W_hh, b_ih, b_hh);
    embed_ln<<<B_ * S_, 256>>>(node_seq, fin_seq, nfin_seq, mda_seq,
                               node_table, fin_table, nfin_table, bert_table,
                               ln_g, ln_b);
    weff_kernel<<<(2 * D_ + 255) / 256, 256>>>(W2, W1);

    // GEMM1: xg = x @ W_ih^T + b_ih    (98304 x 3072 x 992)
    gemm_tf32<<<(B_ * S_ / 128) * NT_, 256>>>(px, pWih, pxg, pbih, KD, KD, NP, NT_, KD);

    // GRU over 6 steps
    for (int t = 0; t < S_; ++t) {
        gemm_tf32<<<(B_ / 128) * NT_, 256>>>(ph, pWhh, pgh, pbhh, KD, KD, NP, NT_, KD);
        gru_cell<<<(B_ * D_ + 255) / 256, 256>>>(seq_len, t);
    }

    // batchnorm stats + folded head
    bn_partial<<<dim3(31, 32), dim3(32, 8)>>>();
    bn_finalize<<<(D_ + 255) / 256, 256>>>(bn_g, bn_b);
    bbn_kernel<<<2, 256>>>(W2, b1, b2);
    logits_kernel<<<(B_ * 32 + 255) / 256, 256>>>((float*)d_out);
}

// round 3
// speedup vs baseline: 1.9782x; 1.9782x over previous
#include <cuda_runtime.h>
#include <cstdint>
#include <math.h>

#define B_   16384
#define S_   6
#define D_   991
#define KD   992          // padded K
#define G3   2973
#define NP   3072         // padded N
#define TM   128
#define TN   128
#define NT_  (NP / TN)    // 24 n-tiles
#define KC   16           // K floats per chunk
#define NCH  (KD / KC)    // 62
#define NST  4
#define LDS_ 20           // padded smem row stride (floats)
#define STF  (TM * LDS_ + TN * LDS_)      // stage floats = 5120
#define SMEM_BYTES (NST * STF * 4)        // 81920

// ------------------- scratch (device globals) ------------------------------
__device__ float g_x  [(size_t)B_ * S_ * KD];
__device__ float g_xg [(size_t)S_ * B_ * NP];
__device__ float g_gh [(size_t)B_ * NP];
__device__ float g_h  [(size_t)B_ * KD];
__device__ float g_out[(size_t)B_ * KD];
__device__ float g_Wih[(size_t)NP * KD];
__device__ float g_Whh[(size_t)NP * KD];
__device__ float g_bih[NP];
__device__ float g_bhh[NP];
__device__ float g_psum[32 * KD];
__device__ float g_psq [32 * KD];
__device__ float g_weff[2 * D_];
__device__ float g_wbn [2 * KD];
__device__ float g_shift[KD];
__device__ float g_bbn [2];

// --------------------------- helpers ---------------------------------------
__device__ __forceinline__ float to_tf32(float x) {
    float y;
    asm("cvt.rna.tf32.f32 %0, %1;" : "=f"(y) : "f"(x));
    return y;
}
__device__ __forceinline__ uint32_t smem_u32(const void* p) {
    uint32_t a;
    asm("{ .reg .u64 t; cvta.to.shared.u64 t, %1; cvt.u32.u64 %0, t; }" : "=r"(a) : "l"(p));
    return a;
}
__device__ __forceinline__ void cp_async16(uint32_t dst, const float* src) {
    asm volatile("cp.async.cg.shared.global [%0], [%1], 16;" :: "r"(dst), "l"(src) : "memory");
}
__device__ __forceinline__ void mma_t(float* c, const uint32_t* a, const uint32_t* b) {
    asm volatile(
        "mma.sync.aligned.m16n8k8.row.col.f32.tf32.tf32.f32 "
        "{%0,%1,%2,%3}, {%4,%5,%6,%7}, {%8,%9}, {%0,%1,%2,%3};"
        : "+f"(c[0]), "+f"(c[1]), "+f"(c[2]), "+f"(c[3])
        : "r"(a[0]), "r"(a[1]), "r"(a[2]), "r"(a[3]), "r"(b[0]), "r"(b[1]));
}

__device__ __forceinline__ float2 block_reduce2(float a, float b) {
    __shared__ float wa[8], wb[8];
    __shared__ float ra, rb;
    int lane = threadIdx.x & 31, w = threadIdx.x >> 5;
#pragma unroll
    for (int o = 16; o; o >>= 1) {
        a += __shfl_down_sync(0xffffffffu, a, o);
        b += __shfl_down_sync(0xffffffffu, b, o);
    }
    if (!lane) { wa[w] = a; wb[w] = b; }
    __syncthreads();
    if (threadIdx.x < 8) { a = wa[threadIdx.x]; b = wb[threadIdx.x]; }
    else { a = 0.f; b = 0.f; }
    if (w == 0) {
#pragma unroll
        for (int o = 4; o; o >>= 1) {
            a += __shfl_down_sync(0xffffffffu, a, o);
            b += __shfl_down_sync(0xffffffffu, b, o);
        }
    }
    if (threadIdx.x == 0) { ra = a; rb = b; }
    __syncthreads();
    return make_float2(ra, rb);
}

// --------------------------- init / pack -----------------------------------
__global__ void zero_h_kernel() {
    size_t i = (size_t)blockIdx.x * 256 + threadIdx.x;
    if (i < (size_t)B_ * KD) g_h[i] = 0.f;
}

__global__ void pad_weights(const float* __restrict__ Wih, const float* __restrict__ Whh,
                            const float* __restrict__ bih, const float* __restrict__ bhh) {
    int i = blockIdx.x * 256 + threadIdx.x;
    if (i >= NP * KD) return;
    int r = i / KD, c = i - r * KD;
    float vi = 0.f, vh = 0.f;
    if (r < G3 && c < D_) {
        vi = to_tf32(Wih[(size_t)r * D_ + c]);
        vh = to_tf32(Whh[(size_t)r * D_ + c]);
    }
    g_Wih[i] = vi;
    g_Whh[i] = vh;
    if (c == 0) {
        g_bih[r] = (r < G3) ? bih[r] : 0.f;
        g_bhh[r] = (r < G3) ? bhh[r] : 0.f;
    }
}

// --------------------------- embed + layernorm -----------------------------
__global__ void embed_ln(const int* __restrict__ ns, const int* __restrict__ fs,
                         const int* __restrict__ nfs, const int* __restrict__ ms,
                         const float* __restrict__ ntab, const float* __restrict__ ftab,
                         const float* __restrict__ nftab, const float* __restrict__ btab,
                         const float* __restrict__ lng, const float* __restrict__ lnb) {
    const int bid = blockIdx.x;          // row = s*B + b
    const int s = bid >> 14;
    const int b = bid & (B_ - 1);
    __shared__ float srow[D_];
    const int q = b * S_ + s;
    const int ni = ns[q], fi = fs[q], nfi = nfs[q], mi = ms[q];
    float s1 = 0.f, s2 = 0.f;
    for (int d = threadIdx.x; d < D_; d += 256) {
        float v;
        if (d < 128)      v = ntab[(size_t)ni * 128 + d];
        else if (d < 212) v = ftab[(size_t)fi * 84 + (d - 128)];
        else if (d < 223) v = nftab[(size_t)nfi * 11 + (d - 212)];
        else              v = btab[(size_t)mi * 768 + (d - 223)];
        srow[d] = v;
        s1 += v; s2 += v * v;
    }
    float2 t = block_reduce2(s1, s2);
    const float mu  = t.x * (1.f / 991.f);
    const float var = fmaxf(t.y * (1.f / 991.f) - mu * mu, 0.f);
    const float rs  = rsqrtf(var + 1e-5f);
    float* xr = g_x + (size_t)bid * KD;
    for (int d = threadIdx.x; d < D_; d += 256)
        xr[d] = to_tf32((srow[d] - mu) * rs * lng[d] + lnb[d]);
    if (threadIdx.x == 0) xr[D_] = 0.f;
}

// --------------------------- tf32 mma.sync GEMM ----------------------------
// C[M, NP] = A[M, KD] @ Bw[NP, KD]^T + bias. 128x128 CTA tile, warp 32x64.
__global__ void __launch_bounds__(256, 2)
gemm_tc(const float* __restrict__ A, const float* __restrict__ Bw,
        float* __restrict__ C, const float* __restrict__ bias) {
    extern __shared__ float smf[];
    const uint32_t sbase = smem_u32(smf);
    const int tid = threadIdx.x;
    const int mt = blockIdx.x / NT_, nt = blockIdx.x % NT_;
    const long m0 = (long)mt * TM;
    const int  n0 = nt * TN;

    // per-thread cp.async slots: 2 A-chunks + 2 B-chunks per stage
    const int crow = tid >> 2;        // 0..63
    const int cseg = tid & 3;         // 0..3
    const float* aS0 = A  + (m0 + crow)      * (long)KD + cseg * 4;
    const float* aS1 = A  + (m0 + crow + 64) * (long)KD + cseg * 4;
    const float* bS0 = Bw + (long)(n0 + crow)      * KD + cseg * 4;
    const float* bS1 = Bw + (long)(n0 + crow + 64) * KD + cseg * 4;
    const uint32_t aO0 = crow * (LDS_ * 4) + cseg * 16;
    const uint32_t aO1 = aO0 + 64 * (LDS_ * 4);
    const uint32_t bO0 = TM * (LDS_ * 4) + aO0;
    const uint32_t bO1 = bO0 + 64 * (LDS_ * 4);

    const int lane = tid & 31, warp = tid >> 5;
    const int mw = (warp >> 1) * 32;   // 4 m-warps
    const int nw = (warp & 1) * 64;    // 2 n-warps
    const int g  = lane >> 2, q = lane & 3;

    float acc[2][8][4];
#pragma unroll
    for (int i = 0; i < 2; i++)
#pragma unroll
        for (int j = 0; j < 8; j++)
#pragma unroll
            for (int e = 0; e < 4; e++) acc[i][j][e] = 0.f;

    // prologue: stages 0..2
#pragma unroll
    for (int c = 0; c < NST - 1; ++c) {
        const uint32_t sb = sbase + (uint32_t)c * STF * 4;
        const int k0 = c * KC;
        cp_async16(sb + aO0, aS0 + k0);
        cp_async16(sb + aO1, aS1 + k0);
        cp_async16(sb + bO0, bS0 + k0);
        cp_async16(sb + bO1, bS1 + k0);
        asm volatile("cp.async.commit_group;" ::: "memory");
    }

#pragma unroll 1
    for (int c = 0; c < NCH; ++c) {
        if (c < NCH - 2)       asm volatile("cp.async.wait_group 2;" ::: "memory");
        else if (c == NCH - 2) asm volatile("cp.async.wait_group 1;" ::: "memory");
        else                   asm volatile("cp.async.wait_group 0;" ::: "memory");
        __syncthreads();

        const int cl = c + NST - 1;
        if (cl < NCH) {
            const uint32_t sb = sbase + (uint32_t)(cl & 3) * STF * 4;
            const int k0 = cl * KC;
            cp_async16(sb + aO0, aS0 + k0);
            cp_async16(sb + aO1, aS1 + k0);
            cp_async16(sb + bO0, bS0 + k0);
            cp_async16(sb + bO1, bS1 + k0);
            asm volatile("cp.async.commit_group;" ::: "memory");
        }

        const uint32_t* sA = (const uint32_t*)(smf + (c & 3) * STF);
        const uint32_t* sB = sA + TM * LDS_;
#pragma unroll
        for (int ks = 0; ks < 2; ++ks) {
            const int k0 = ks * 8 + q;
            uint32_t a[2][4];
#pragma unroll
            for (int i = 0; i < 2; i++) {
                const int r0 = mw + i * 16 + g;
                a[i][0] = sA[r0 * LDS_ + k0];
                a[i][1] = sA[(r0 + 8) * LDS_ + k0];
                a[i][2] = sA[r0 * LDS_ + k0 + 4];
                a[i][3] = sA[(r0 + 8) * LDS_ + k0 + 4];
            }
#pragma unroll
            for (int j = 0; j < 8; j++) {
                const int n = nw + j * 8 + g;
                uint32_t b[2];
                b[0] = sB[n * LDS_ + k0];
                b[1] = sB[n * LDS_ + k0 + 4];
                mma_t(acc[0][j], a[0], b);
                mma_t(acc[1][j], a[1], b);
            }
        }
        __syncthreads();
    }

    // epilogue: direct register -> gmem with fused bias
#pragma unroll
    for (int i = 0; i < 2; i++) {
        const long r0 = m0 + mw + i * 16 + g;
#pragma unroll
        for (int j = 0; j < 8; j++) {
            const int colg = n0 + nw + j * 8 + 2 * q;
            const float2 bb = *(const float2*)(bias + colg);
            float2 v0, v1;
            v0.x = acc[i][j][0] + bb.x; v0.y = acc[i][j][1] + bb.y;
            v1.x = acc[i][j][2] + bb.x; v1.y = acc[i][j][3] + bb.y;
            *(float2*)(C + r0 * NP + colg)       = v0;
            *(float2*)(C + (r0 + 8) * NP + colg) = v1;
        }
    }
}

// --------------------------- GRU cell --------------------------------------
__global__ void gru_cell(const int* __restrict__ seq_len, int t, int first) {
    unsigned i = blockIdx.x * 256u + threadIdx.x;
    if (i >= (unsigned)B_ * D_) return;
    int b = i / D_;
    int d = i - b * D_;
    const float* xg = g_xg + (size_t)t * B_ * NP + (size_t)b * NP;
    float hr, hz, hn, hp;
    if (first) {
        hr = g_bhh[d]; hz = g_bhh[D_ + d]; hn = g_bhh[2 * D_ + d];
        hp = 0.f;
    } else {
        const float* gh = g_gh + (size_t)b * NP;
        hr = gh[d]; hz = gh[D_ + d]; hn = gh[2 * D_ + d];
        hp = g_h[(size_t)b * KD + d];
    }
    float r = 1.f / (1.f + expf(-(xg[d]        + hr)));
    float z = 1.f / (1.f + expf(-(xg[D_ + d]   + hz)));
    float n = tanhf(xg[2 * D_ + d] + r * hn);
    float hv = (1.f - z) * n + z * hp;
    g_h[(size_t)b * KD + d] = to_tf32(hv);   // tf32-round for next GEMM
    if (seq_len[b] - 1 == t) g_out[(size_t)b * KD + d] = hv;
}

// --------------------------- batchnorm + folded head -----------------------
__global__ void bn_partial() {
    __shared__ float ss[8][33], sq[8][33];
    int col = blockIdx.x * 32 + threadIdx.x;
    int ty = threadIdx.y;
    float s = 0.f, q = 0.f;
    for (int r = blockIdx.y * 8 + ty; r < B_; r += 256) {
        float v = g_out[(size_t)r * KD + col];
        s += v; q += v * v;
    }
    ss[ty][threadIdx.x] = s; sq[ty][threadIdx.x] = q;
    __syncthreads();
    if (ty == 0) {
        float S = 0.f, Q = 0.f;
#pragma unroll
        for (int k = 0; k < 8; k++) { S += ss[k][threadIdx.x]; Q += sq[k][threadIdx.x]; }
        g_psum[blockIdx.y * KD + col] = S;
        g_psq [blockIdx.y * KD + col] = Q;
    }
}

__global__ void weff_kernel(const float* __restrict__ W2, const float* __restrict__ W1) {
    int gw   = blockIdx.x * 8 + (threadIdx.x >> 5);
    int lane = threadIdx.x & 31;
    if (gw >= 2 * D_) return;
    int o = gw / D_, d = gw - o * D_;
    float acc = 0.f;
    for (int j = lane; j < 2 * D_; j += 32)
        acc += W2[o * (2 * D_) + j] * W1[(size_t)j * D_ + d];
#pragma unroll
    for (int off = 16; off; off >>= 1) acc += __shfl_down_sync(0xffffffffu, acc, off);
    if (lane == 0) g_weff[gw] = acc;
}

__global__ void bn_finalize(const float* __restrict__ bn_g, const float* __restrict__ bn_b) {
    int d = blockIdx.x * 256 + threadIdx.x;
    if (d >= D_) return;
    float s = 0.f, q = 0.f;
#pragma unroll
    for (int p = 0; p < 32; p++) { s += g_psum[p * KD + d]; q += g_psq[p * KD + d]; }
    float mu  = s * (1.f / 16384.f);
    float var = fmaxf(q * (1.f / 16384.f) - mu * mu, 0.f);
    float sc  = bn_g[d] * rsqrtf(var + 1e-4f);
    g_shift[d]    = bn_b[d] - mu * sc;
    g_wbn[d]      = g_weff[d]      * sc;
    g_wbn[KD + d] = g_weff[D_ + d] * sc;
}

__global__ void bbn_kernel(const float* __restrict__ W2, const float* __restrict__ b1,
                           const float* __restrict__ b2) {
    int o = blockIdx.x;
    float acc = 0.f;
    for (int j = threadIdx.x; j < 2 * D_; j += 256) acc += W2[o * (2 * D_) + j] * b1[j];
    for (int d = threadIdx.x; d < D_; d += 256)     acc += g_weff[o * D_ + d] * g_shift[d];
    float2 t = block_reduce2(acc, 0.f);
    if (threadIdx.x == 0) g_bbn[o] = t.x + b2[o];
}

__global__ void logits_kernel(float* __restrict__ out) {
    int gw   = (blockIdx.x * 256 + threadIdx.x) >> 5;
    int lane = threadIdx.x & 31;
    if (gw >= B_) return;
    const float* row = g_out + (size_t)gw * KD;
    float a0 = 0.f, a1 = 0.f;
    for (int d = lane; d < D_; d += 32) {
        float v = row[d];
        a0 += v * g_wbn[d];
        a1 += v * g_wbn[KD + d];
    }
#pragma unroll
    for (int o = 16; o; o >>= 1) {
        a0 += __shfl_down_sync(0xffffffffu, a0, o);
        a1 += __shfl_down_sync(0xffffffffu, a1, o);
    }
    if (lane == 0) {
        out[2 * gw]     = a0 + g_bbn[0];
        out[2 * gw + 1] = a1 + g_bbn[1];
    }
}

// --------------------------- launch -----------------------------------------
extern "C" void kernel_launch(void* const* d_in, const int* in_sizes, int n_in,
                              void* d_out, int out_size) {
    const int*   node_seq   = (const int*)d_in[0];
    const int*   fin_seq    = (const int*)d_in[1];
    const int*   nfin_seq   = (const int*)d_in[2];
    const int*   mda_seq    = (const int*)d_in[3];
    const int*   seq_len    = (const int*)d_in[4];
    const float* node_table = (const float*)d_in[5];
    const float* fin_table  = (const float*)d_in[6];
    const float* nfin_table = (const float*)d_in[7];
    const float* bert_table = (const float*)d_in[8];
    const float* ln_g = (const float*)d_in[9];
    const float* ln_b = (const float*)d_in[10];
    const float* W_ih = (const float*)d_in[11];
    const float* W_hh = (const float*)d_in[12];
    const float* b_ih = (const float*)d_in[13];
    const float* b_hh = (const float*)d_in[14];
    const float* bn_g = (const float*)d_in[15];
    const float* bn_b = (const float*)d_in[16];
    const float* W1   = (const float*)d_in[17];
    const float* b1   = (const float*)d_in[18];
    const float* W2   = (const float*)d_in[19];
    const float* b2   = (const float*)d_in[20];

    float *px, *pxg, *pgh, *ph, *pWih, *pWhh, *pbih, *pbhh;
    cudaGetSymbolAddress((void**)&px,   g_x);
    cudaGetSymbolAddress((void**)&pxg,  g_xg);
    cudaGetSymbolAddress((void**)&pgh,  g_gh);
    cudaGetSymbolAddress((void**)&ph,   g_h);
    cudaGetSymbolAddress((void**)&pWih, g_Wih);
    cudaGetSymbolAddress((void**)&pWhh, g_Whh);
    cudaGetSymbolAddress((void**)&pbih, g_bih);
    cudaGetSymbolAddress((void**)&pbhh, g_bhh);

    cudaFuncSetAttribute(gemm_tc, cudaFuncAttributeMaxDynamicSharedMemorySize, SMEM_BYTES);

    zero_h_kernel<<<(B_ * KD + 255) / 256, 256>>>();
    pad_weights<<<(NP * KD + 255) / 256, 256>>>(W_ih, W_hh, b_ih, b_hh);
    embed_ln<<<B_ * S_, 256>>>(node_seq, fin_seq, nfin_seq, mda_seq,
                               node_table, fin_table, nfin_table, bert_table,
                               ln_g, ln_b);
    weff_kernel<<<(2 * D_ + 7) / 8, 256>>>(W2, W1);

    // GEMM1: xg = x @ W_ih^T + b_ih   (98304 x 3072 x 992)
    gemm_tc<<<(B_ * S_ / TM) * NT_, 256, SMEM_BYTES>>>(px, pWih, pxg, pbih);

    // GRU: t=0 uses h0=0 => gh = b_hh, no GEMM needed
    gru_cell<<<(B_ * D_ + 255) / 256, 256>>>(seq_len, 0, 1);
    for (int t = 1; t < S_; ++t) {
        gemm_tc<<<(B_ / TM) * NT_, 256, SMEM_BYTES>>>(ph, pWhh, pgh, pbhh);
        gru_cell<<<(B_ * D_ + 255) / 256, 256>>>(seq_len, t, 0);
    }

    // batchnorm stats + folded head
    bn_partial<<<dim3(31, 32), dim3(32, 8)>>>();
    bn_finalize<<<(D_ + 255) / 256, 256>>>(bn_g, bn_b);
    bbn_kernel<<<2, 256>>>(W2, b1, b2);
    logits_kernel<<<(B_ * 32 + 255) / 256, 256>>>((float*)d_out);
}

// round 4
// speedup vs baseline: 4.1555x; 2.1006x over previous
#include <cuda_runtime.h>
#include <cuda_fp16.h>
#include <cstdint>
#include <math.h>

#define B_   16384
#define S_   6
#define D_   991
#define KD   992          // fp32 out-row stride for g_out
#define KH   1024         // padded K for half GEMM operands
#define G3   2973
#define NP   3072         // padded N
#define TM   128
#define TN   128
#define NT_  (NP / TN)    // 24 n-tiles
#define KCH  64           // K halfs per chunk (128 bytes/row)
#define NCHh (KH / KCH)   // 16 chunks
#define NST  3
#define STB  ((TM + TN) * 128)        // 32768 bytes per stage
#define SMEMB (NST * STB)             // 98304

// ------------------- scratch (device globals) ------------------------------
__device__ __half g_x  [(size_t)B_ * S_ * KH];
__device__ __half g_xg [(size_t)S_ * B_ * NP];
__device__ __half g_gh [(size_t)B_ * NP];
__device__ __half g_h  [(size_t)B_ * KH];
__device__ float  g_out[(size_t)B_ * KD];
__device__ __half g_Wih[(size_t)NP * KH];
__device__ __half g_Whh[(size_t)NP * KH];
__device__ float  g_bih[NP];
__device__ float  g_bhh[NP];
__device__ float  g_psum[32 * KD];
__device__ float  g_psq [32 * KD];
__device__ float  g_weff[2 * D_];
__device__ float  g_wbn [2 * KD];
__device__ float  g_shift[KD];
__device__ float  g_bbn [2];

// --------------------------- helpers ---------------------------------------
__device__ __forceinline__ uint32_t smem_u32(const void* p) {
    uint32_t a;
    asm("{ .reg .u64 t; cvta.to.shared.u64 t, %1; cvt.u32.u64 %0, t; }" : "=r"(a) : "l"(p));
    return a;
}
__device__ __forceinline__ void cp_async16(uint32_t dst, const void* src) {
    asm volatile("cp.async.cg.shared.global [%0], [%1], 16;" :: "r"(dst), "l"(src) : "memory");
}
#define CP_COMMIT() asm volatile("cp.async.commit_group;" ::: "memory")
#define CP_WAIT(n)  asm volatile("cp.async.wait_group %0;" :: "n"(n) : "memory")

__device__ __forceinline__ void ldm4(uint32_t* r, uint32_t addr) {
    asm volatile("ldmatrix.sync.aligned.m8n8.x4.shared.b16 {%0,%1,%2,%3}, [%4];"
                 : "=r"(r[0]), "=r"(r[1]), "=r"(r[2]), "=r"(r[3]) : "r"(addr));
}
__device__ __forceinline__ void mma_h(float* c, const uint32_t* a, const uint32_t* b) {
    asm volatile(
        "mma.sync.aligned.m16n8k16.row.col.f32.f16.f16.f32 "
        "{%0,%1,%2,%3}, {%4,%5,%6,%7}, {%8,%9}, {%0,%1,%2,%3};"
        : "+f"(c[0]), "+f"(c[1]), "+f"(c[2]), "+f"(c[3])
        : "r"(a[0]), "r"(a[1]), "r"(a[2]), "r"(a[3]), "r"(b[0]), "r"(b[1]));
}

__device__ __forceinline__ float2 block_reduce2(float a, float b) {
    __shared__ float wa[8], wb[8];
    __shared__ float ra, rb;
    int lane = threadIdx.x & 31, w = threadIdx.x >> 5;
#pragma unroll
    for (int o = 16; o; o >>= 1) {
        a += __shfl_down_sync(0xffffffffu, a, o);
        b += __shfl_down_sync(0xffffffffu, b, o);
    }
    if (!lane) { wa[w] = a; wb[w] = b; }
    __syncthreads();
    if (threadIdx.x < 8) { a = wa[threadIdx.x]; b = wb[threadIdx.x]; }
    else { a = 0.f; b = 0.f; }
    if (w == 0) {
#pragma unroll
        for (int o = 4; o; o >>= 1) {
            a += __shfl_down_sync(0xffffffffu, a, o);
            b += __shfl_down_sync(0xffffffffu, b, o);
        }
    }
    if (threadIdx.x == 0) { ra = a; rb = b; }
    __syncthreads();
    return make_float2(ra, rb);
}

// --------------------------- init / pack -----------------------------------
__global__ void zero_h_kernel() {
    size_t i = (size_t)blockIdx.x * 256 + threadIdx.x;
    if (i < (size_t)B_ * KH / 8) {
        uint4 z = {0, 0, 0, 0};
        ((uint4*)g_h)[i] = z;
    }
}

__global__ void pad_weights(const float* __restrict__ Wih, const float* __restrict__ Whh,
                            const float* __restrict__ bih, const float* __restrict__ bhh) {
    size_t i = (size_t)blockIdx.x * 256 + threadIdx.x;
    if (i >= (size_t)NP * KH) return;
    int r = (int)(i / KH), c = (int)(i - (size_t)r * KH);
    float vi = 0.f, vh = 0.f;
    if (r < G3 && c < D_) {
        vi = Wih[(size_t)r * D_ + c];
        vh = Whh[(size_t)r * D_ + c];
    }
    g_Wih[i] = __float2half_rn(vi);
    g_Whh[i] = __float2half_rn(vh);
    if (c == 0) {
        g_bih[r] = (r < G3) ? bih[r] : 0.f;
        g_bhh[r] = (r < G3) ? bhh[r] : 0.f;
    }
}

// --------------------------- embed + layernorm -----------------------------
__global__ void embed_ln(const int* __restrict__ ns, const int* __restrict__ fs,
                         const int* __restrict__ nfs, const int* __restrict__ ms,
                         const float* __restrict__ ntab, const float* __restrict__ ftab,
                         const float* __restrict__ nftab, const float* __restrict__ btab,
                         const float* __restrict__ lng, const float* __restrict__ lnb) {
    const int bid = blockIdx.x;          // row = s*B + b
    const int s = bid >> 14;
    const int b = bid & (B_ - 1);
    __shared__ float srow[D_];
    const int q = b * S_ + s;
    const int ni = ns[q], fi = fs[q], nfi = nfs[q], mi = ms[q];
    float s1 = 0.f, s2 = 0.f;
    for (int d = threadIdx.x; d < D_; d += 256) {
        float v;
        if (d < 128)      v = ntab[(size_t)ni * 128 + d];
        else if (d < 212) v = ftab[(size_t)fi * 84 + (d - 128)];
        else if (d < 223) v = nftab[(size_t)nfi * 11 + (d - 212)];
        else              v = btab[(size_t)mi * 768 + (d - 223)];
        srow[d] = v;
        s1 += v; s2 += v * v;
    }
    float2 t = block_reduce2(s1, s2);
    const float mu  = t.x * (1.f / 991.f);
    const float var = fmaxf(t.y * (1.f / 991.f) - mu * mu, 0.f);
    const float rs  = rsqrtf(var + 1e-5f);
    __half* xr = g_x + (size_t)bid * KH;
    for (int d = threadIdx.x; d < KH; d += 256) {
        float v = (d < D_) ? (srow[d] - mu) * rs * lng[d] + lnb[d] : 0.f;
        xr[d] = __float2half_rn(v);
    }
}

// --------------------------- fp16 mma.sync GEMM ----------------------------
// C(half)[M, NP] = A(half)[M, KH] @ Bw(half)[NP, KH]^T + bias(fp32).
// 128x128 CTA tile, 8 warps of 32x64, m16n8k16, ldmatrix, 3-stage cp.async.
__global__ void __launch_bounds__(256, 2)
gemm_h(const __half* __restrict__ A, const __half* __restrict__ Bw,
       __half* __restrict__ C, const float* __restrict__ bias) {
    extern __shared__ char sm[];
    const uint32_t sb0 = smem_u32(sm);
    const int tid = threadIdx.x;
    const int mt = blockIdx.x / NT_, nt = blockIdx.x % NT_;
    const long m0 = (long)mt * TM;
    const int  n0 = nt * TN;

    // cp.async slots: 4 A granules + 4 B granules (16B each) per thread/stage
    uint32_t aOffG[4], bOffG[4], aDst[4], bDst[4];
#pragma unroll
    for (int t = 0; t < 4; ++t) {
        int gidx = tid + t * 256;           // 0..1023
        int row = gidx >> 3, cg = gidx & 7;
        aOffG[t] = (uint32_t)((m0 + row) * KH + cg * 8);
        bOffG[t] = (uint32_t)((long)(n0 + row) * KH + cg * 8);
        uint32_t sw = (uint32_t)((cg ^ (row & 7)) << 4);
        aDst[t] = row * 128 + sw;
        bDst[t] = TM * 128 + row * 128 + sw;
    }

    const int lane = tid & 31, warp = tid >> 5;
    const int mw = (warp >> 1) * 32;
    const int nw = (warp & 1) * 64;
    const int g  = lane >> 2, q = lane & 3;

    // ldmatrix row/parity precompute
    uint32_t aRow[2];
#pragma unroll
    for (int i = 0; i < 2; ++i) aRow[i] = mw + i * 16 + (lane & 15);
    const uint32_t aPar = (uint32_t)(lane >> 4);
    uint32_t bRow[4];
#pragma unroll
    for (int jp = 0; jp < 4; ++jp)
        bRow[jp] = nw + jp * 16 + (lane & 7) + ((lane >> 4) << 3);
    const uint32_t bPar = (uint32_t)((lane >> 3) & 1);

    float acc[2][8][4];
#pragma unroll
    for (int i = 0; i < 2; i++)
#pragma unroll
        for (int j = 0; j < 8; j++)
#pragma unroll
            for (int e = 0; e < 4; e++) acc[i][j][e] = 0.f;

    // prologue: chunks 0,1 -> stages 0,1
#pragma unroll
    for (int c = 0; c < 2; ++c) {
        const uint32_t st = sb0 + c * STB;
        const int k0 = c * KCH;
#pragma unroll
        for (int t = 0; t < 4; ++t) {
            cp_async16(st + aDst[t], A  + aOffG[t] + k0);
            cp_async16(st + bDst[t], Bw + bOffG[t] + k0);
        }
        CP_COMMIT();
    }

#pragma unroll 1
    for (int c = 0; c < NCHh; ++c) {
        if (c + 2 < NCHh) {
            const uint32_t st = sb0 + ((c + 2) % 3) * STB;
            const int k0 = (c + 2) * KCH;
#pragma unroll
            for (int t = 0; t < 4; ++t) {
                cp_async16(st + aDst[t], A  + aOffG[t] + k0);
                cp_async16(st + bDst[t], Bw + bOffG[t] + k0);
            }
            CP_COMMIT();
            CP_WAIT(2);
        } else if (c + 2 == NCHh) {
            CP_WAIT(1);
        } else {
            CP_WAIT(0);
        }
        __syncthreads();

        const uint32_t sA  = sb0 + (c % 3) * STB;
        const uint32_t sBq = sA + TM * 128;
#pragma unroll
        for (int ks = 0; ks < 4; ++ks) {
            uint32_t a[2][4], bf[4][4];
#pragma unroll
            for (int i = 0; i < 2; ++i) {
                uint32_t kg = 2 * ks + aPar;
                ldm4(a[i], sA + aRow[i] * 128 + ((kg ^ (aRow[i] & 7)) << 4));
            }
#pragma unroll
            for (int jp = 0; jp < 4; ++jp) {
                uint32_t kg = 2 * ks + bPar;
                ldm4(bf[jp], sBq + bRow[jp] * 128 + ((kg ^ (bRow[jp] & 7)) << 4));
            }
#pragma unroll
            for (int i = 0; i < 2; ++i)
#pragma unroll
                for (int j = 0; j < 8; ++j)
                    mma_h(acc[i][j], a[i], &bf[j >> 1][(j & 1) * 2]);
        }
        __syncthreads();
    }

    // epilogue: fp32 bias add, store half2
#pragma unroll
    for (int i = 0; i < 2; ++i) {
        const long r0 = m0 + mw + i * 16 + g;
#pragma unroll
        for (int j = 0; j < 8; ++j) {
            const int colg = n0 + nw + j * 8 + 2 * q;
            const float2 bb = *(const float2*)(bias + colg);
            *(__half2*)(C + r0 * NP + colg) =
                __floats2half2_rn(acc[i][j][0] + bb.x, acc[i][j][1] + bb.y);
            *(__half2*)(C + (r0 + 8) * NP + colg) =
                __floats2half2_rn(acc[i][j][2] + bb.x, acc[i][j][3] + bb.y);
        }
    }
}

// --------------------------- GRU cell --------------------------------------
__global__ void gru_cell(const int* __restrict__ seq_len, int t, int first) {
    unsigned i = blockIdx.x * 256u + threadIdx.x;
    if (i >= (unsigned)(B_ * D_)) return;
    int b = i / D_;
    int d = i - b * D_;
    const __half* xg = g_xg + (size_t)t * B_ * NP + (size_t)b * NP;
    float hr, hz, hn, hp;
    if (first) {
        hr = g_bhh[d]; hz = g_bhh[D_ + d]; hn = g_bhh[2 * D_ + d];
        hp = 0.f;
    } else {
        const __half* gh = g_gh + (size_t)b * NP;
        hr = __half2float(gh[d]);
        hz = __half2float(gh[D_ + d]);
        hn = __half2float(gh[2 * D_ + d]);
        hp = __half2float(g_h[(size_t)b * KH + d]);
    }
    float r = 1.f / (1.f + expf(-(__half2float(xg[d])        + hr)));
    float z = 1.f / (1.f + expf(-(__half2float(xg[D_ + d])   + hz)));
    float n = tanhf(__half2float(xg[2 * D_ + d]) + r * hn);
    float hv = (1.f - z) * n + z * hp;
    g_h[(size_t)b * KH + d] = __float2half_rn(hv);
    if (seq_len[b] - 1 == t) g_out[(size_t)b * KD + d] = hv;
}

// --------------------------- batchnorm + folded head -----------------------
__global__ void bn_partial() {
    __shared__ float ss[8][33], sq[8][33];
    int col = blockIdx.x * 32 + threadIdx.x;
    int ty = threadIdx.y;
    float s = 0.f, q = 0.f;
    for (int r = blockIdx.y * 8 + ty; r < B_; r += 256) {
        float v = g_out[(size_t)r * KD + col];
        s += v; q += v * v;
    }
    ss[ty][threadIdx.x] = s; sq[ty][threadIdx.x] = q;
    __syncthreads();
    if (ty == 0) {
        float S = 0.f, Q = 0.f;
#pragma unroll
        for (int k = 0; k < 8; k++) { S += ss[k][threadIdx.x]; Q += sq[k][threadIdx.x]; }
        g_psum[blockIdx.y * KD + col] = S;
        g_psq [blockIdx.y * KD + col] = Q;
    }
}

__global__ void weff_kernel(const float* __restrict__ W2, const float* __restrict__ W1) {
    int gw   = blockIdx.x * 8 + (threadIdx.x >> 5);
    int lane = threadIdx.x & 31;
    if (gw >= 2 * D_) return;
    int o = gw / D_, d = gw - o * D_;
    float acc = 0.f;
    for (int j = lane; j < 2 * D_; j += 32)
        acc += W2[o * (2 * D_) + j] * W1[(size_t)j * D_ + d];
#pragma unroll
    for (int off = 16; off; off >>= 1) acc += __shfl_down_sync(0xffffffffu, acc, off);
    if (lane == 0) g_weff[gw] = acc;
}

__global__ void bn_finalize(const float* __restrict__ bn_g, const float* __restrict__ bn_b) {
    int d = blockIdx.x * 256 + threadIdx.x;
    if (d >= D_) return;
    float s = 0.f, q = 0.f;
#pragma unroll
    for (int p = 0; p < 32; p++) { s += g_psum[p * KD + d]; q += g_psq[p * KD + d]; }
    float mu  = s * (1.f / 16384.f);
    float var = fmaxf(q * (1.f / 16384.f) - mu * mu, 0.f);
    float sc  = bn_g[d] * rsqrtf(var + 1e-4f);
    g_shift[d]    = bn_b[d] - mu * sc;
    g_wbn[d]      = g_weff[d]      * sc;
    g_wbn[KD + d] = g_weff[D_ + d] * sc;
}

__global__ void bbn_kernel(const float* __restrict__ W2, const float* __restrict__ b1,
                           const float* __restrict__ b2) {
    int o = blockIdx.x;
    float acc = 0.f;
    for (int j = threadIdx.x; j < 2 * D_; j += 256) acc += W2[o * (2 * D_) + j] * b1[j];
    for (int d = threadIdx.x; d < D_; d += 256)     acc += g_weff[o * D_ + d] * g_shift[d];
    float2 t = block_reduce2(acc, 0.f);
    if (threadIdx.x == 0) g_bbn[o] = t.x + b2[o];
}

__global__ void logits_kernel(float* __restrict__ out) {
    int gw   = (blockIdx.x * 256 + threadIdx.x) >> 5;
    int lane = threadIdx.x & 31;
    if (gw >= B_) return;
    const float* row = g_out + (size_t)gw * KD;
    float a0 = 0.f, a1 = 0.f;
    for (int d = lane; d < D_; d += 32) {
        float v = row[d];
        a0 += v * g_wbn[d];
        a1 += v * g_wbn[KD + d];
    }
#pragma unroll
    for (int o = 16; o; o >>= 1) {
        a0 += __shfl_down_sync(0xffffffffu, a0, o);
        a1 += __shfl_down_sync(0xffffffffu, a1, o);
    }
    if (lane == 0) {
        out[2 * gw]     = a0 + g_bbn[0];
        out[2 * gw + 1] = a1 + g_bbn[1];
    }
}

// --------------------------- launch -----------------------------------------
extern "C" void kernel_launch(void* const* d_in, const int* in_sizes, int n_in,
                              void* d_out, int out_size) {
    const int*   node_seq   = (const int*)d_in[0];
    const int*   fin_seq    = (const int*)d_in[1];
    const int*   nfin_seq   = (const int*)d_in[2];
    const int*   mda_seq    = (const int*)d_in[3];
    const int*   seq_len    = (const int*)d_in[4];
    const float* node_table = (const float*)d_in[5];
    const float* fin_table  = (const float*)d_in[6];
    const float* nfin_table = (const float*)d_in[7];
    const float* bert_table = (const float*)d_in[8];
    const float* ln_g = (const float*)d_in[9];
    const float* ln_b = (const float*)d_in[10];
    const float* W_ih = (const float*)d_in[11];
    const float* W_hh = (const float*)d_in[12];
    const float* b_ih = (const float*)d_in[13];
    const float* b_hh = (const float*)d_in[14];
    const float* bn_g = (const float*)d_in[15];
    const float* bn_b = (const float*)d_in[16];
    const float* W1   = (const float*)d_in[17];
    const float* b1   = (const float*)d_in[18];
    const float* W2   = (const float*)d_in[19];
    const float* b2   = (const float*)d_in[20];

    __half *px, *pxg, *pgh, *ph, *pWih, *pWhh;
    float *pbih, *pbhh;
    cudaGetSymbolAddress((void**)&px,   g_x);
    cudaGetSymbolAddress((void**)&pxg,  g_xg);
    cudaGetSymbolAddress((void**)&pgh,  g_gh);
    cudaGetSymbolAddress((void**)&ph,   g_h);
    cudaGetSymbolAddress((void**)&pWih, g_Wih);
    cudaGetSymbolAddress((void**)&pWhh, g_Whh);
    cudaGetSymbolAddress((void**)&pbih, g_bih);
    cudaGetSymbolAddress((void**)&pbhh, g_bhh);

    cudaFuncSetAttribute(gemm_h, cudaFuncAttributeMaxDynamicSharedMemorySize, SMEMB);

    zero_h_kernel<<<(B_ * KH / 8 + 255) / 256, 256>>>();
    pad_weights<<<(NP * KH + 255) / 256, 256>>>(W_ih, W_hh, b_ih, b_hh);
    embed_ln<<<B_ * S_, 256>>>(node_seq, fin_seq, nfin_seq, mda_seq,
                               node_table, fin_table, nfin_table, bert_table,
                               ln_g, ln_b);
    weff_kernel<<<(2 * D_ + 7) / 8, 256>>>(W2, W1);

    // GEMM1: xg = x @ W_ih^T + b_ih   (98304 x 3072 x 1024, fp16 in/out)
    gemm_h<<<(B_ * S_ / TM) * NT_, 256, SMEMB>>>(px, pWih, pxg, pbih);

    // GRU: t=0 uses h0=0 => gh = b_hh, no GEMM needed
    gru_cell<<<(B_ * D_ + 255) / 256, 256>>>(seq_len, 0, 1);
    for (int t = 1; t < S_; ++t) {
        gemm_h<<<(B_ / TM) * NT_, 256, SMEMB>>>(ph, pWhh, pgh, pbhh);
        gru_cell<<<(B_ * D_ + 255) / 256, 256>>>(seq_len, t, 0);
    }

    // batchnorm stats + folded head
    bn_partial<<<dim3(31, 32), dim3(32, 8)>>>();
    bn_finalize<<<(D_ + 255) / 256, 256>>>(bn_g, bn_b);
    bbn_kernel<<<2, 256>>>(W2, b1, b2);
    logits_kernel<<<(B_ * 32 + 255) / 256, 256>>>((float*)d_out);
}

// round 5
// speedup vs baseline: 6.8684x; 1.6528x over previous
#include <cuda_runtime.h>
#include <cuda_fp16.h>
#include <cstdint>
#include <math.h>

#define B_   16384
#define S_   6
#define D_   991
#define KD   992          // fp32 out-row stride for g_out
#define KH   1024         // padded K for half GEMM operands
#define G3   2973
#define NP   3072         // padded N
#define TM   128
#define TN   128
#define NT_  (NP / TN)    // 24 n-tiles
#define KCH  64           // K halfs per chunk (128 bytes/row)
#define NCHh (KH / KCH)   // 16 chunks
#define NST  3
#define STB  ((TM + TN) * 128)        // 32768 bytes per stage
#define SMEMB (NST * STB)             // 98304

// ------------------- scratch (device globals) ------------------------------
__device__ __half g_x  [(size_t)B_ * S_ * KH];
__device__ __half g_xg [(size_t)S_ * B_ * NP];
__device__ __half g_gh [(size_t)B_ * NP];
__device__ __half g_h  [(size_t)B_ * KH];
__device__ float  g_out[(size_t)B_ * KD];
__device__ __half g_Wih[(size_t)NP * KH];
__device__ __half g_Whh[(size_t)NP * KH];
__device__ float  g_bih[NP];
__device__ float  g_bhh[NP];
__device__ float  g_psum[32 * KD];
__device__ float  g_psq [32 * KD];
__device__ float  g_weff[2 * D_];
__device__ float  g_wbn [2 * KD];
__device__ float  g_shift[KD];
__device__ float  g_bbn [2];
// ragged-batch bookkeeping (permuted row space, sorted by descending seq_len)
__device__ int    g_idx[B_];    // position p -> batch b
__device__ int    g_sln[B_];    // position p -> seq_len
__device__ int    g_cnt[8];     // g_cnt[s] = #rows active at step s (prefix)

// --------------------------- helpers ---------------------------------------
__device__ __forceinline__ uint32_t smem_u32(const void* p) {
    uint32_t a;
    asm("{ .reg .u64 t; cvta.to.shared.u64 t, %1; cvt.u32.u64 %0, t; }" : "=r"(a) : "l"(p));
    return a;
}
__device__ __forceinline__ void cp_async16(uint32_t dst, const void* src) {
    asm volatile("cp.async.cg.shared.global [%0], [%1], 16;" :: "r"(dst), "l"(src) : "memory");
}
#define CP_COMMIT() asm volatile("cp.async.commit_group;" ::: "memory")
#define CP_WAIT(n)  asm volatile("cp.async.wait_group %0;" :: "n"(n) : "memory")

__device__ __forceinline__ void ldm4(uint32_t* r, uint32_t addr) {
    asm volatile("ldmatrix.sync.aligned.m8n8.x4.shared.b16 {%0,%1,%2,%3}, [%4];"
                 : "=r"(r[0]), "=r"(r[1]), "=r"(r[2]), "=r"(r[3]) : "r"(addr));
}
__device__ __forceinline__ void mma_h(float* c, const uint32_t* a, const uint32_t* b) {
    asm volatile(
        "mma.sync.aligned.m16n8k16.row.col.f32.f16.f16.f32 "
        "{%0,%1,%2,%3}, {%4,%5,%6,%7}, {%8,%9}, {%0,%1,%2,%3};"
        : "+f"(c[0]), "+f"(c[1]), "+f"(c[2]), "+f"(c[3])
        : "r"(a[0]), "r"(a[1]), "r"(a[2]), "r"(a[3]), "r"(b[0]), "r"(b[1]));
}

__device__ __forceinline__ float2 block_reduce2(float a, float b) {
    __shared__ float wa[8], wb[8];
    __shared__ float ra, rb;
    int lane = threadIdx.x & 31, w = threadIdx.x >> 5;
#pragma unroll
    for (int o = 16; o; o >>= 1) {
        a += __shfl_down_sync(0xffffffffu, a, o);
        b += __shfl_down_sync(0xffffffffu, b, o);
    }
    if (!lane) { wa[w] = a; wb[w] = b; }
    __syncthreads();
    if (threadIdx.x < 8) { a = wa[threadIdx.x]; b = wb[threadIdx.x]; }
    else { a = 0.f; b = 0.f; }
    if (w == 0) {
#pragma unroll
        for (int o = 4; o; o >>= 1) {
            a += __shfl_down_sync(0xffffffffu, a, o);
            b += __shfl_down_sync(0xffffffffu, b, o);
        }
    }
    if (threadIdx.x == 0) { ra = a; rb = b; }
    __syncthreads();
    return make_float2(ra, rb);
}

// --------------------------- deterministic counting sort --------------------
// Sort batch indices by DESCENDING seq_len. Stable (by batch id), no atomics.
__global__ void __launch_bounds__(1024)
sort_kernel(const int* __restrict__ seq_len) {
    __shared__ int cnts[1024][6];   // 24 KB
    __shared__ int tot[6], base[6];
    const int tid = threadIdx.x;
    const int b0 = tid * 16;
    int lc[6] = {0, 0, 0, 0, 0, 0};
#pragma unroll
    for (int k = 0; k < 16; ++k) {
        int v = seq_len[b0 + k] - 1;     // 0..5
        lc[v]++;
    }
#pragma unroll
    for (int v = 0; v < 6; ++v) cnts[tid][v] = lc[v];
    __syncthreads();
    if (tid < 6) {                       // serial exclusive scan per bucket
        int run = 0;
        for (int i = 0; i < 1024; ++i) {
            int c = cnts[i][tid];
            cnts[i][tid] = run;
            run += c;
        }
        tot[tid] = run;
    }
    __syncthreads();
    if (tid == 0) {
        int acc = 0;
        for (int v = 5; v >= 0; --v) { base[v] = acc; acc += tot[v]; }
        for (int s = 0; s < 6; ++s) {    // rows active at step s: seq_len-1 >= s
            int c = 0;
            for (int v = s; v < 6; ++v) c += tot[v];
            g_cnt[s] = c;
        }
    }
    __syncthreads();
    int off[6];
#pragma unroll
    for (int v = 0; v < 6; ++v) off[v] = base[v] + cnts[tid][v];
#pragma unroll
    for (int k = 0; k < 16; ++k) {
        int b = b0 + k;
        int v = seq_len[b] - 1;
        int p = off[v]++;
        g_idx[p] = b;
        g_sln[p] = v + 1;
    }
}

// --------------------------- init / pack -----------------------------------
__global__ void pad_weights(const float* __restrict__ Wih, const float* __restrict__ Whh,
                            const float* __restrict__ bih, const float* __restrict__ bhh) {
    size_t i = (size_t)blockIdx.x * 256 + threadIdx.x;
    if (i >= (size_t)NP * KH) return;
    int r = (int)(i / KH), c = (int)(i - (size_t)r * KH);
    float vi = 0.f, vh = 0.f;
    if (r < G3 && c < D_) {
        vi = Wih[(size_t)r * D_ + c];
        vh = Whh[(size_t)r * D_ + c];
    }
    g_Wih[i] = __float2half_rn(vi);
    g_Whh[i] = __float2half_rn(vh);
    if (c == 0) {
        g_bih[r] = (r < G3) ? bih[r] : 0.f;
        g_bhh[r] = (r < G3) ? bhh[r] : 0.f;
    }
}

// --------------------------- embed + layernorm (permuted rows) -------------
__global__ void embed_ln(const int* __restrict__ ns, const int* __restrict__ fs,
                         const int* __restrict__ nfs, const int* __restrict__ ms,
                         const float* __restrict__ ntab, const float* __restrict__ ftab,
                         const float* __restrict__ nftab, const float* __restrict__ btab,
                         const float* __restrict__ lng, const float* __restrict__ lnb) {
    const int bid = blockIdx.x;          // row = s*B + p
    const int s = bid >> 14;
    const int p = bid & (B_ - 1);
    if (p >= g_cnt[s]) return;           // inactive row at this step
    const int b = g_idx[p];
    __shared__ float srow[D_];
    const int q = b * S_ + s;
    const int ni = ns[q], fi = fs[q], nfi = nfs[q], mi = ms[q];
    float s1 = 0.f, s2 = 0.f;
    for (int d = threadIdx.x; d < D_; d += 256) {
        float v;
        if (d < 128)      v = ntab[(size_t)ni * 128 + d];
        else if (d < 212) v = ftab[(size_t)fi * 84 + (d - 128)];
        else if (d < 223) v = nftab[(size_t)nfi * 11 + (d - 212)];
        else              v = btab[(size_t)mi * 768 + (d - 223)];
        srow[d] = v;
        s1 += v; s2 += v * v;
    }
    float2 t = block_reduce2(s1, s2);
    const float mu  = t.x * (1.f / 991.f);
    const float var = fmaxf(t.y * (1.f / 991.f) - mu * mu, 0.f);
    const float rs  = rsqrtf(var + 1e-5f);
    __half* xr = g_x + (size_t)bid * KH;
    for (int d = threadIdx.x; d < KH; d += 256) {
        float v = (d < D_) ? (srow[d] - mu) * rs * lng[d] + lnb[d] : 0.f;
        xr[d] = __float2half_rn(v);
    }
}

// --------------------------- fp16 mma.sync GEMM ----------------------------
// C(half)[M, NP] = A(half)[M, KH] @ Bw(half)[NP, KH]^T + bias(fp32).
// step < 0: GEMM1 (m-tile grid = S*128, per-s active prefix from g_cnt[s]).
// step >= 0: recurrent GEMM (m-tile grid = 128, active prefix g_cnt[step]).
__global__ void __launch_bounds__(256, 2)
gemm_h(const __half* __restrict__ A, const __half* __restrict__ Bw,
       __half* __restrict__ C, const float* __restrict__ bias, int step) {
    const int mt = blockIdx.x / NT_, nt = blockIdx.x % NT_;
    {
        int mtl, cnt;
        if (step < 0) { mtl = mt & 127; cnt = g_cnt[mt >> 7]; }
        else          { mtl = mt;       cnt = g_cnt[step]; }
        if (mtl * TM >= cnt) return;     // inactive m-tile
    }
    extern __shared__ char sm[];
    const uint32_t sb0 = smem_u32(sm);
    const int tid = threadIdx.x;
    const long m0 = (long)mt * TM;
    const int  n0 = nt * TN;

    // cp.async slots: 4 A granules + 4 B granules (16B each) per thread/stage
    uint32_t aDst[4], bDst[4];
    size_t aOffG[4], bOffG[4];
#pragma unroll
    for (int t = 0; t < 4; ++t) {
        int gidx = tid + t * 256;           // 0..1023
        int row = gidx >> 3, cg = gidx & 7;
        aOffG[t] = (size_t)(m0 + row) * KH + cg * 8;
        bOffG[t] = (size_t)(n0 + row) * KH + cg * 8;
        uint32_t sw = (uint32_t)((cg ^ (row & 7)) << 4);
        aDst[t] = row * 128 + sw;
        bDst[t] = TM * 128 + row * 128 + sw;
    }

    const int lane = tid & 31, warp = tid >> 5;
    const int mw = (warp >> 1) * 32;
    const int nw = (warp & 1) * 64;
    const int g  = lane >> 2, q = lane & 3;

    uint32_t aRow[2];
#pragma unroll
    for (int i = 0; i < 2; ++i) aRow[i] = mw + i * 16 + (lane & 15);
    const uint32_t aPar = (uint32_t)(lane >> 4);
    uint32_t bRow[4];
#pragma unroll
    for (int jp = 0; jp < 4; ++jp)
        bRow[jp] = nw + jp * 16 + (lane & 7) + ((lane >> 4) << 3);
    const uint32_t bPar = (uint32_t)((lane >> 3) & 1);

    float acc[2][8][4];
#pragma unroll
    for (int i = 0; i < 2; i++)
#pragma unroll
        for (int j = 0; j < 8; j++)
#pragma unroll
            for (int e = 0; e < 4; e++) acc[i][j][e] = 0.f;

    // prologue: chunks 0,1 -> stages 0,1
#pragma unroll
    for (int c = 0; c < 2; ++c) {
        const uint32_t st = sb0 + c * STB;
        const int k0 = c * KCH;
#pragma unroll
        for (int t = 0; t < 4; ++t) {
            cp_async16(st + aDst[t], A  + aOffG[t] + k0);
            cp_async16(st + bDst[t], Bw + bOffG[t] + k0);
        }
        CP_COMMIT();
    }

#pragma unroll 1
    for (int c = 0; c < NCHh; ++c) {
        if (c + 2 < NCHh) {
            const uint32_t st = sb0 + ((c + 2) % 3) * STB;
            const int k0 = (c + 2) * KCH;
#pragma unroll
            for (int t = 0; t < 4; ++t) {
                cp_async16(st + aDst[t], A  + aOffG[t] + k0);
                cp_async16(st + bDst[t], Bw + bOffG[t] + k0);
            }
            CP_COMMIT();
            CP_WAIT(2);
        } else if (c + 2 == NCHh) {
            CP_WAIT(1);
        } else {
            CP_WAIT(0);
        }
        __syncthreads();

        const uint32_t sA  = sb0 + (c % 3) * STB;
        const uint32_t sBq = sA + TM * 128;
#pragma unroll
        for (int ks = 0; ks < 4; ++ks) {
            uint32_t a[2][4], bf[4][4];
#pragma unroll
            for (int i = 0; i < 2; ++i) {
                uint32_t kg = 2 * ks + aPar;
                ldm4(a[i], sA + aRow[i] * 128 + ((kg ^ (aRow[i] & 7)) << 4));
            }
#pragma unroll
            for (int jp = 0; jp < 4; ++jp) {
                uint32_t kg = 2 * ks + bPar;
                ldm4(bf[jp], sBq + bRow[jp] * 128 + ((kg ^ (bRow[jp] & 7)) << 4));
            }
#pragma unroll
            for (int i = 0; i < 2; ++i)
#pragma unroll
                for (int j = 0; j < 8; ++j)
                    mma_h(acc[i][j], a[i], &bf[j >> 1][(j & 1) * 2]);
        }
        __syncthreads();
    }

    // epilogue: fp32 bias add, store half2
#pragma unroll
    for (int i = 0; i < 2; ++i) {
        const long r0 = m0 + mw + i * 16 + g;
#pragma unroll
        for (int j = 0; j < 8; ++j) {
            const int colg = n0 + nw + j * 8 + 2 * q;
            const float2 bb = *(const float2*)(bias + colg);
            *(__half2*)(C + r0 * NP + colg) =
                __floats2half2_rn(acc[i][j][0] + bb.x, acc[i][j][1] + bb.y);
            *(__half2*)(C + (r0 + 8) * NP + colg) =
                __floats2half2_rn(acc[i][j][2] + bb.x, acc[i][j][3] + bb.y);
        }
    }
}

// --------------------------- GRU cell (permuted rows) ----------------------
__global__ void gru_cell(int t, int first) {
    unsigned i = blockIdx.x * 256u + threadIdx.x;
    if (i >= (unsigned)(B_ * D_)) return;
    int p = i / D_;
    int d = i - p * D_;
    if (p >= g_cnt[t]) return;          // sequence already finished
    const __half* xg = g_xg + (size_t)t * B_ * NP + (size_t)p * NP;
    float hr, hz, hn, hp;
    if (first) {
        hr = g_bhh[d]; hz = g_bhh[D_ + d]; hn = g_bhh[2 * D_ + d];
        hp = 0.f;
    } else {
        const __half* gh = g_gh + (size_t)p * NP;
        hr = __half2float(gh[d]);
        hz = __half2float(gh[D_ + d]);
        hn = __half2float(gh[2 * D_ + d]);
        hp = __half2float(g_h[(size_t)p * KH + d]);
    }
    float r = 1.f / (1.f + expf(-(__half2float(xg[d])        + hr)));
    float z = 1.f / (1.f + expf(-(__half2float(xg[D_ + d])   + hz)));
    float n = tanhf(__half2float(xg[2 * D_ + d]) + r * hn);
    float hv = (1.f - z) * n + z * hp;
    g_h[(size_t)p * KH + d] = __float2half_rn(hv);
    if (g_sln[p] - 1 == t) g_out[(size_t)p * KD + d] = hv;
}

// --------------------------- batchnorm + folded head -----------------------
__global__ void bn_partial() {
    __shared__ float ss[8][33], sq[8][33];
    int col = blockIdx.x * 32 + threadIdx.x;
    int ty = threadIdx.y;
    float s = 0.f, q = 0.f;
    for (int r = blockIdx.y * 8 + ty; r < B_; r += 256) {
        float v = g_out[(size_t)r * KD + col];
        s += v; q += v * v;
    }
    ss[ty][threadIdx.x] = s; sq[ty][threadIdx.x] = q;
    __syncthreads();
    if (ty == 0) {
        float S = 0.f, Q = 0.f;
#pragma unroll
        for (int k = 0; k < 8; k++) { S += ss[k][threadIdx.x]; Q += sq[k][threadIdx.x]; }
        g_psum[blockIdx.y * KD + col] = S;
        g_psq [blockIdx.y * KD + col] = Q;
    }
}

__global__ void weff_kernel(const float* __restrict__ W2, const float* __restrict__ W1) {
    int gw   = blockIdx.x * 8 + (threadIdx.x >> 5);
    int lane = threadIdx.x & 31;
    if (gw >= 2 * D_) return;
    int o = gw / D_, d = gw - o * D_;
    float acc = 0.f;
    for (int j = lane; j < 2 * D_; j += 32)
        acc += W2[o * (2 * D_) + j] * W1[(size_t)j * D_ + d];
#pragma unroll
    for (int off = 16; off; off >>= 1) acc += __shfl_down_sync(0xffffffffu, acc, off);
    if (lane == 0) g_weff[gw] = acc;
}

__global__ void bn_finalize(const float* __restrict__ bn_g, const float* __restrict__ bn_b) {
    int d = blockIdx.x * 256 + threadIdx.x;
    if (d >= D_) return;
    float s = 0.f, q = 0.f;
#pragma unroll
    for (int p = 0; p < 32; p++) { s += g_psum[p * KD + d]; q += g_psq[p * KD + d]; }
    float mu  = s * (1.f / 16384.f);
    float var = fmaxf(q * (1.f / 16384.f) - mu * mu, 0.f);
    float sc  = bn_g[d] * rsqrtf(var + 1e-4f);
    g_shift[d]    = bn_b[d] - mu * sc;
    g_wbn[d]      = g_weff[d]      * sc;
    g_wbn[KD + d] = g_weff[D_ + d] * sc;
}

__global__ void bbn_kernel(const float* __restrict__ W2, const float* __restrict__ b1,
                           const float* __restrict__ b2) {
    int o = blockIdx.x;
    float acc = 0.f;
    for (int j = threadIdx.x; j < 2 * D_; j += 256) acc += W2[o * (2 * D_) + j] * b1[j];
    for (int d = threadIdx.x; d < D_; d += 256)     acc += g_weff[o * D_ + d] * g_shift[d];
    float2 t = block_reduce2(acc, 0.f);
    if (threadIdx.x == 0) g_bbn[o] = t.x + b2[o];
}

__global__ void logits_kernel(float* __restrict__ out) {
    int gw   = (blockIdx.x * 256 + threadIdx.x) >> 5;
    int lane = threadIdx.x & 31;
    if (gw >= B_) return;
    const float* row = g_out + (size_t)gw * KD;
    float a0 = 0.f, a1 = 0.f;
    for (int d = lane; d < D_; d += 32) {
        float v = row[d];
        a0 += v * g_wbn[d];
        a1 += v * g_wbn[KD + d];
    }
#pragma unroll
    for (int o = 16; o; o >>= 1) {
        a0 += __shfl_down_sync(0xffffffffu, a0, o);
        a1 += __shfl_down_sync(0xffffffffu, a1, o);
    }
    if (lane == 0) {
        int b = g_idx[gw];              // scatter back to original batch order
        out[2 * b]     = a0 + g_bbn[0];
        out[2 * b + 1] = a1 + g_bbn[1];
    }
}

// --------------------------- launch -----------------------------------------
extern "C" void kernel_launch(void* const* d_in, const int* in_sizes, int n_in,
                              void* d_out, int out_size) {
    const int*   node_seq   = (const int*)d_in[0];
    const int*   fin_seq    = (const int*)d_in[1];
    const int*   nfin_seq   = (const int*)d_in[2];
    const int*   mda_seq    = (const int*)d_in[3];
    const int*   seq_len    = (const int*)d_in[4];
    const float* node_table = (const float*)d_in[5];
    const float* fin_table  = (const float*)d_in[6];
    const float* nfin_table = (const float*)d_in[7];
    const float* bert_table = (const float*)d_in[8];
    const float* ln_g = (const float*)d_in[9];
    const float* ln_b = (const float*)d_in[10];
    const float* W_ih = (const float*)d_in[11];
    const float* W_hh = (const float*)d_in[12];
    const float* b_ih = (const float*)d_in[13];
    const float* b_hh = (const float*)d_in[14];
    const float* bn_g = (const float*)d_in[15];
    const float* bn_b = (const float*)d_in[16];
    const float* W1   = (const float*)d_in[17];
    const float* b1   = (const float*)d_in[18];
    const float* W2   = (const float*)d_in[19];
    const float* b2   = (const float*)d_in[20];

    __half *px, *pxg, *pgh, *ph, *pWih, *pWhh;
    float *pbih, *pbhh;
    cudaGetSymbolAddress((void**)&px,   g_x);
    cudaGetSymbolAddress((void**)&pxg,  g_xg);
    cudaGetSymbolAddress((void**)&pgh,  g_gh);
    cudaGetSymbolAddress((void**)&ph,   g_h);
    cudaGetSymbolAddress((void**)&pWih, g_Wih);
    cudaGetSymbolAddress((void**)&pWhh, g_Whh);
    cudaGetSymbolAddress((void**)&pbih, g_bih);
    cudaGetSymbolAddress((void**)&pbhh, g_bhh);

    cudaFuncSetAttribute(gemm_h, cudaFuncAttributeMaxDynamicSharedMemorySize, SMEMB);

    sort_kernel<<<1, 1024>>>(seq_len);
    pad_weights<<<(NP * KH + 255) / 256, 256>>>(W_ih, W_hh, b_ih, b_hh);
    embed_ln<<<B_ * S_, 256>>>(node_seq, fin_seq, nfin_seq, mda_seq,
                               node_table, fin_table, nfin_table, bert_table,
                               ln_g, ln_b);
    weff_kernel<<<(2 * D_ + 7) / 8, 256>>>(W2, W1);

    // GEMM1: xg = x @ W_ih^T + b_ih  (ragged: per-s active prefix)
    gemm_h<<<(B_ * S_ / TM) * NT_, 256, SMEMB>>>(px, pWih, pxg, pbih, -1);

    // GRU: t=0 uses h0=0 => gh = b_hh, no GEMM needed
    gru_cell<<<(B_ * D_ + 255) / 256, 256>>>(0, 1);
    for (int t = 1; t < S_; ++t) {
        gemm_h<<<(B_ / TM) * NT_, 256, SMEMB>>>(ph, pWhh, pgh, pbhh, t);
        gru_cell<<<(B_ * D_ + 255) / 256, 256>>>(t, 0);
    }

    // batchnorm stats + folded head
    bn_partial<<<dim3(31, 32), dim3(32, 8)>>>();
    bn_finalize<<<(D_ + 255) / 256, 256>>>(bn_g, bn_b);
    bbn_kernel<<<2, 256>>>(W2, b1, b2);
    logits_kernel<<<(B_ * 32 + 255) / 256, 256>>>((float*)d_out);
}